// round 2
// baseline (speedup 1.0000x reference)
#include <cuda_runtime.h>
#include <cstdint>

// Problem constants
#define BB 64
#define SS 512
#define EE 256
#define HH 512
#define FH 2048  // 4*H

// Scratch state (allowed: __device__ globals, no allocation)
__device__ float g_h[2][BB * HH];
__device__ float g_c[2][BB * HH];
__device__ float g_u[(size_t)SS * BB * FH];  // u_all laid out [s][b][4H]

// ---------------------------------------------------------------------------
// Packed fp32x2 FMA (Blackwell): doubles fp32 FMA rate vs FFMA-3reg (rt=2).
// ---------------------------------------------------------------------------
__device__ __forceinline__ void ffma2(unsigned long long& d,
                                      unsigned long long a,
                                      unsigned long long b) {
    asm volatile("fma.rn.f32x2 %0, %1, %2, %0;" : "+l"(d) : "l"(a), "l"(b));
}
__device__ __forceinline__ float lo32(unsigned long long v) {
    return __uint_as_float((unsigned)(v & 0xffffffffull));
}
__device__ __forceinline__ float hi32(unsigned long long v) {
    return __uint_as_float((unsigned)(v >> 32));
}
__device__ __forceinline__ float sigmoidf_(float x) {
    return 1.0f / (1.0f + expf(-x));
}

// ---------------------------------------------------------------------------
// Zero initial state h0 = c0 = 0 (ping buffer 0)
// ---------------------------------------------------------------------------
__global__ void init_state_kernel() {
    int i = blockIdx.x * blockDim.x + threadIdx.x;
    if (i < BB * HH) {
        g_h[0][i] = 0.0f;
        g_c[0][i] = 0.0f;
    }
}

// ---------------------------------------------------------------------------
// u_all GEMM: g_u[s][b][f] = inputs[b,s,:] . U_all_w[f,:] + U_all_b[f]
// M = B*S = 32768 (rows m = b*S+s), N = 4H = 2048, K = E = 256.
// Block tile: 32 (16 batch-pairs) x 128 cols. 256 threads.
// Thread = (m-pair ty, col-lane tx), cols tx + 16*n8 (interleaved so that
// smem rows accessed by a warp are consecutive -> conflict-free with pad 2).
// ---------------------------------------------------------------------------
#define UG_BM 32
#define UG_BN 128
#define UG_KC 32

__global__ __launch_bounds__(256) void u_gemm_kernel(
    const float* __restrict__ X,   // inputs [B*S, E]
    const float* __restrict__ W,   // U_all_w [4H, E]
    const float* __restrict__ Bv)  // U_all_b [4H]
{
    __shared__ float2 sA[16][UG_KC];        // [mpair][k] = (x_even, x_odd)
    __shared__ float2 sB[UG_BN][UG_KC + 2]; // duplicated (w,w), padded rows

    int t = threadIdx.x;
    int tx = t & 15;   // column lane
    int ty = t >> 4;   // m-pair
    int m0 = blockIdx.x * UG_BM;
    int n0 = blockIdx.y * UG_BN;

    unsigned long long acc[8];
#pragma unroll
    for (int i = 0; i < 8; i++) acc[i] = 0ull;

    for (int k0 = 0; k0 < EE; k0 += UG_KC) {
#pragma unroll
        for (int r = 0; r < 2; r++) {
            int i = t + 256 * r;       // 512 float2 of A
            int p = i >> 5, k = i & 31;
            float x0 = X[(size_t)(m0 + 2 * p) * EE + k0 + k];
            float x1 = X[(size_t)(m0 + 2 * p + 1) * EE + k0 + k];
            sA[p][k] = make_float2(x0, x1);
        }
#pragma unroll
        for (int r = 0; r < 16; r++) {
            int i = t + 256 * r;       // 4096 float2 of B
            int n = i >> 5, k = i & 31;
            float w = W[(size_t)(n0 + n) * EE + k0 + k];
            sB[n][k] = make_float2(w, w);
        }
        __syncthreads();
#pragma unroll
        for (int k = 0; k < UG_KC; k += 2) {
            unsigned long long a0 = *(const unsigned long long*)&sA[ty][k];
            unsigned long long a1 = *(const unsigned long long*)&sA[ty][k + 1];
#pragma unroll
            for (int n8 = 0; n8 < 8; n8++) {
                const unsigned long long* bp =
                    (const unsigned long long*)&sB[tx + 16 * n8][k];
                ffma2(acc[n8], a0, bp[0]);
                ffma2(acc[n8], a1, bp[1]);
            }
        }
        __syncthreads();
    }

    // Epilogue: add bias, scatter to g_u[s][b][n]
#pragma unroll
    for (int e = 0; e < 2; e++) {
        int m = m0 + 2 * ty + e;
        int b = m >> 9;       // m / S   (S = 512)
        int s = m & 511;      // m % S
        float* urow = g_u + ((size_t)s * BB + b) * FH;
#pragma unroll
        for (int n8 = 0; n8 < 8; n8++) {
            int n = n0 + tx + 16 * n8;
            float v = (e ? hi32(acc[n8]) : lo32(acc[n8])) + Bv[n];
            urow[n] = v;
        }
    }
}

// ---------------------------------------------------------------------------
// One recurrence step. Block = (16 j-columns) x (32 batches). Grid (32, 2).
// Thread (bp=ty, j=tx) computes, for its 2 packed batches and column j:
//   4 gate dots over h (W_all rows g*H+j) + 1 decay dot over c (W_d row j),
// then the full gate nonlinearity — no intra-step synchronization needed.
// Weights staged in smem DUPLICATED as (w,w) float2 so FMA operands are
// pre-packed; rows padded by 2 float2 (stride 68 words -> 4-bank steps,
// conflict-free across the 16 consecutive-row lanes).
// ---------------------------------------------------------------------------
#define ST_KC 32

__global__ __launch_bounds__(256) void step_kernel(
    const float* __restrict__ Wall,   // [4H, H]
    const float* __restrict__ Wall_b, // [4H]
    const float* __restrict__ Wd,     // [H, H]
    const float* __restrict__ Wd_b,   // [H]
    const float* __restrict__ ts,     // [B, S]
    float* __restrict__ out,          // [B, S, H]
    int s, int par)
{
    __shared__ float2 sh[16][ST_KC];          // [bpair][k]
    __shared__ float2 sc[16][ST_KC];
    __shared__ float2 sw[5][16][ST_KC + 2];   // duplicated weights, padded

    const float* h = g_h[par];
    const float* c = g_c[par];
    float* hn = g_h[par ^ 1];
    float* cn = g_c[par ^ 1];

    int t = threadIdx.x;
    int tx = t & 15;   // j within tile
    int ty = t >> 4;   // batch pair
    int j0 = blockIdx.x * 16;
    int b0 = blockIdx.y * 32;

    unsigned long long a0 = 0, a1 = 0, a2 = 0, a3 = 0, a4 = 0;

    for (int k0 = 0; k0 < HH; k0 += ST_KC) {
#pragma unroll
        for (int r = 0; r < 2; r++) {
            int i = t + 256 * r;        // 512 float2 each for h, c
            int p = i >> 5, k = i & 31;
            int b = b0 + 2 * p;
            sh[p][k] = make_float2(h[b * HH + k0 + k], h[(b + 1) * HH + k0 + k]);
            sc[p][k] = make_float2(c[b * HH + k0 + k], c[(b + 1) * HH + k0 + k]);
        }
#pragma unroll
        for (int r = 0; r < 10; r++) {
            int i = t + 256 * r;        // 2560 float2 of weights (5 sets x 16 j x 32 k)
            int g = i >> 9;             // 0..4
            int jj = (i >> 5) & 15;
            int k = i & 31;
            float w;
            if (g < 4) w = Wall[(size_t)(g * HH + j0 + jj) * HH + k0 + k];
            else       w = Wd[(size_t)(j0 + jj) * HH + k0 + k];
            sw[g][jj][k] = make_float2(w, w);
        }
        __syncthreads();
#pragma unroll
        for (int k = 0; k < ST_KC; k += 2) {
            unsigned long long h0 = *(const unsigned long long*)&sh[ty][k];
            unsigned long long h1 = *(const unsigned long long*)&sh[ty][k + 1];
            unsigned long long c0 = *(const unsigned long long*)&sc[ty][k];
            unsigned long long c1 = *(const unsigned long long*)&sc[ty][k + 1];
            const unsigned long long* w0 = (const unsigned long long*)&sw[0][tx][k];
            const unsigned long long* w1 = (const unsigned long long*)&sw[1][tx][k];
            const unsigned long long* w2 = (const unsigned long long*)&sw[2][tx][k];
            const unsigned long long* w3 = (const unsigned long long*)&sw[3][tx][k];
            const unsigned long long* w4 = (const unsigned long long*)&sw[4][tx][k];
            ffma2(a0, h0, w0[0]); ffma2(a0, h1, w0[1]);
            ffma2(a1, h0, w1[0]); ffma2(a1, h1, w1[1]);
            ffma2(a2, h0, w2[0]); ffma2(a2, h1, w2[1]);
            ffma2(a3, h0, w3[0]); ffma2(a3, h1, w3[1]);
            ffma2(a4, c0, w4[0]); ffma2(a4, c1, w4[1]);
        }
        __syncthreads();
    }

    // Gate epilogue
    int j = j0 + tx;
    const float* u = g_u + (size_t)s * BB * FH;
    float bf = Wall_b[j];
    float bi = Wall_b[HH + j];
    float bo = Wall_b[2 * HH + j];
    float bg = Wall_b[3 * HH + j];
    float bd = Wd_b[j];

#pragma unroll
    for (int e = 0; e < 2; e++) {
        int b = b0 + 2 * ty + e;
        float pf = (e ? hi32(a0) : lo32(a0)) + bf + u[(size_t)b * FH + j];
        float pi = (e ? hi32(a1) : lo32(a1)) + bi + u[(size_t)b * FH + HH + j];
        float po = (e ? hi32(a2) : lo32(a2)) + bo + u[(size_t)b * FH + 2 * HH + j];
        float pg = (e ? hi32(a3) : lo32(a3)) + bg + u[(size_t)b * FH + 3 * HH + j];
        float dd = (e ? hi32(a4) : lo32(a4)) + bd;

        float cs1 = tanhf(dd);
        float cold = c[b * HH + j];
        float tb = ts[b * SS + s];
        float cadj = (cold - cs1) + cs1 * tb;

        float fg = sigmoidf_(pf);
        float ig = sigmoidf_(pi);
        float og = sigmoidf_(po);
        float cg = sigmoidf_(pg);

        float cnew = fg * cadj + ig * cg;
        float hnew = og * tanhf(cnew);

        cn[b * HH + j] = cnew;
        hn[b * HH + j] = hnew;
        out[((size_t)b * SS + s) * HH + j] = hnew;
    }
}

// ---------------------------------------------------------------------------
// Copy final h, c to the output tail (reference returns (outputs, h, c)).
// After 512 steps (even), final state is in ping buffer 0.
// ---------------------------------------------------------------------------
__global__ void finalize_kernel(float* __restrict__ out) {
    int i = blockIdx.x * blockDim.x + threadIdx.x;
    if (i < BB * HH) {
        out[(size_t)BB * SS * HH + i] = g_h[0][i];
        out[(size_t)BB * SS * HH + (size_t)BB * HH + i] = g_c[0][i];
    }
}

// ---------------------------------------------------------------------------
// Launch
// ---------------------------------------------------------------------------
extern "C" void kernel_launch(void* const* d_in, const int* in_sizes, int n_in,
                              void* d_out, int out_size) {
    const float* X      = (const float*)d_in[0];  // inputs [B,S,E]
    const float* ts     = (const float*)d_in[1];  // timestamps [B,S]
    const float* Wall   = (const float*)d_in[2];  // [4H,H]
    const float* Wall_b = (const float*)d_in[3];  // [4H]
    const float* U      = (const float*)d_in[4];  // [4H,E]
    const float* Ub     = (const float*)d_in[5];  // [4H]
    const float* Wd     = (const float*)d_in[6];  // [H,H]
    const float* Wdb    = (const float*)d_in[7];  // [H]
    float* out = (float*)d_out;

    init_state_kernel<<<(BB * HH + 255) / 256, 256>>>();

    dim3 gu(BB * SS / UG_BM, FH / UG_BN);  // (1024, 16)
    u_gemm_kernel<<<gu, 256>>>(X, U, Ub);

    dim3 gs(HH / 16, BB / 32);             // (32, 2)
    for (int s = 0; s < SS; s++) {
        step_kernel<<<gs, 256>>>(Wall, Wall_b, Wd, Wdb, ts, out, s, s & 1);
    }

    long long need = (long long)BB * SS * HH + 2LL * BB * HH;
    if ((long long)out_size >= need) {
        finalize_kernel<<<(BB * HH + 255) / 256, 256>>>(out);
    }
}

// round 4
// speedup vs baseline: 1.8725x; 1.8725x over previous
#include <cuda_runtime.h>
#include <cstdint>

#define BB 64
#define SS 512
#define EE 256
#define HH 512
#define FH 2048
#define NBLK 128

// Packed state: [bpair][k] float2 = (val_b_even, val_b_odd)
__device__ float2 g_hp[2][32 * HH];
__device__ float2 g_cp[2][32 * HH];
// u_all repacked: [s][gate][bpair][j] float2
__device__ float2 g_u2[(size_t)SS * 4 * 32 * HH];
__device__ unsigned g_cnt;
__device__ unsigned g_gen;

// ---------------------------------------------------------------------------
__device__ __forceinline__ void ffma2(unsigned long long& d,
                                      unsigned long long a,
                                      unsigned long long b) {
    asm volatile("fma.rn.f32x2 %0, %1, %2, %0;" : "+l"(d) : "l"(a), "l"(b));
}
__device__ __forceinline__ float lo32(unsigned long long v) {
    return __uint_as_float((unsigned)(v & 0xffffffffull));
}
__device__ __forceinline__ float hi32(unsigned long long v) {
    return __uint_as_float((unsigned)(v >> 32));
}
__device__ __forceinline__ float sigmoidf_(float x) {
    return 1.0f / (1.0f + expf(-x));
}

// ---------------------------------------------------------------------------
__global__ void init_state_kernel() {
    int i = blockIdx.x * blockDim.x + threadIdx.x;
    if (i < 32 * HH) {
        g_hp[0][i] = make_float2(0.f, 0.f);
        g_cp[0][i] = make_float2(0.f, 0.f);
    }
    if (i == 0) { g_cnt = 0; g_gen = 0; }
}

// ---------------------------------------------------------------------------
// u_all GEMM: rows are (s, batch-pair) so output packs batch pairs.
// Block tile: 32 batches (16 pairs) at fixed s  x  128 cols. 256 threads.
// ---------------------------------------------------------------------------
#define UG_KC 32

__global__ __launch_bounds__(256) void u_gemm_kernel(
    const float* __restrict__ X,   // inputs [B, S, E]
    const float* __restrict__ W,   // U_all_w [4H, E]
    const float* __restrict__ Bv)  // U_all_b [4H]
{
    __shared__ float2 sA[16][UG_KC];
    __shared__ float2 sB[128][UG_KC + 2];

    int t = threadIdx.x;
    int tx = t & 15;
    int ty = t >> 4;
    int s  = blockIdx.x >> 1;
    int bh = blockIdx.x & 1;
    int b0 = bh * 32;
    int n0 = blockIdx.y * 128;

    unsigned long long acc[8];
#pragma unroll
    for (int i = 0; i < 8; i++) acc[i] = 0ull;

    for (int k0 = 0; k0 < EE; k0 += UG_KC) {
#pragma unroll
        for (int r = 0; r < 2; r++) {
            int i = t + 256 * r;
            int p = i >> 5, k = i & 31;
            int b = b0 + 2 * p;
            float x0 = X[((size_t)b * SS + s) * EE + k0 + k];
            float x1 = X[((size_t)(b + 1) * SS + s) * EE + k0 + k];
            sA[p][k] = make_float2(x0, x1);
        }
#pragma unroll
        for (int r = 0; r < 16; r++) {
            int i = t + 256 * r;
            int n = i >> 5, k = i & 31;
            float w = W[(size_t)(n0 + n) * EE + k0 + k];
            sB[n][k] = make_float2(w, w);
        }
        __syncthreads();
#pragma unroll
        for (int k = 0; k < UG_KC; k += 2) {
            unsigned long long a0 = *(const unsigned long long*)&sA[ty][k];
            unsigned long long a1 = *(const unsigned long long*)&sA[ty][k + 1];
#pragma unroll
            for (int n8 = 0; n8 < 8; n8++) {
                const unsigned long long* bp =
                    (const unsigned long long*)&sB[tx + 16 * n8][k];
                ffma2(acc[n8], a0, bp[0]);
                ffma2(acc[n8], a1, bp[1]);
            }
        }
        __syncthreads();
    }

    int bpG = bh * 16 + ty;
#pragma unroll
    for (int n8 = 0; n8 < 8; n8++) {
        int n = n0 + tx + 16 * n8;
        int g = n >> 9;
        int j = n & 511;
        float b = Bv[n];
        g_u2[((size_t)(s * 4 + g) * 32 + bpG) * HH + j] =
            make_float2(lo32(acc[n8]) + b, hi32(acc[n8]) + b);
    }
}

// ---------------------------------------------------------------------------
// Persistent recurrence kernel. Grid = 128 blocks (64 j-tiles x 2 b-halves),
// 256 threads = (kh 2) x (bp 16) x (j 8). Weights live in smem for ALL steps.
// Per step: stage h/c chunks (double-buffered) from L2, FFMA2 dots, gate
// epilogue, software grid barrier.
// ---------------------------------------------------------------------------
__global__ __launch_bounds__(256, 1) void lstm_persistent(
    const float* __restrict__ Wall,   // [4H, H]
    const float* __restrict__ Wall_b, // [4H]
    const float* __restrict__ Wd,     // [H, H]
    const float* __restrict__ Wd_b,   // [H]
    const float* __restrict__ ts,     // [B, S]
    float* __restrict__ out)          // [B, S, H]
{
    extern __shared__ float2 smem[];
    float2* SW = smem;                       // [5][8][514] duplicated weights
    float2* SH = smem + 5 * 8 * 514;         // [2][16][66] h staging
    float2* SC = SH + 2 * 16 * 66;           // [2][16][66] c staging
    unsigned long long* RED = (unsigned long long*)SH;  // reused post-loop

    const int t  = threadIdx.x;
    const int kh = t >> 7;
    const int r  = t & 127;
    const int bp = r >> 3;
    const int j7 = r & 7;
    const int jt = blockIdx.x >> 1;
    const int bh = blockIdx.x & 1;
    const int j0 = jt * 8;
    const int j  = j0 + j7;
    const int bpG = bh * 16 + bp;

    // One-time: load weight slice, duplicated as (w,w)
#pragma unroll 4
    for (int it = 0; it < 80; it++) {
        int i = t + 256 * it;
        int g = i >> 12;
        int jj = (i >> 9) & 7;
        int k = i & 511;
        float w = (g < 4) ? Wall[(size_t)(g * HH + j0 + jj) * HH + k]
                          : Wd[(size_t)(j0 + jj) * HH + k];
        SW[(g * 8 + jj) * 514 + k] = make_float2(w, w);
    }
    float bf = 0.f, bi = 0.f, bo = 0.f, bg = 0.f, bd = 0.f;
    if (kh == 0) {
        bf = Wall_b[j];
        bi = Wall_b[HH + j];
        bo = Wall_b[2 * HH + j];
        bg = Wall_b[3 * HH + j];
        bd = Wd_b[j];
    }
    __syncthreads();

    for (int s = 0; s < SS; s++) {
        const int par = s & 1;
        const float2* hp = g_hp[par];
        const float2* cp = g_cp[par];
        float2* hn = g_hp[par ^ 1];
        float2* cn = g_cp[par ^ 1];

        // Prefetch epilogue operands (latency hidden under k-loop)
        float2 uf, ui, uo, ug, cold;
        float t0v = 0.f, t1v = 0.f;
        if (kh == 0) {
            const float2* ub = g_u2 + (size_t)s * 4 * 32 * HH;
            uf = __ldcs(ub + ((size_t)0 * 32 + bpG) * HH + j);
            ui = __ldcs(ub + ((size_t)1 * 32 + bpG) * HH + j);
            uo = __ldcs(ub + ((size_t)2 * 32 + bpG) * HH + j);
            ug = __ldcs(ub + ((size_t)3 * 32 + bpG) * HH + j);
            cold = __ldcg(cp + bpG * HH + j);
            t0v = __ldg(ts + (size_t)(2 * bpG) * SS + s);
            t1v = __ldg(ts + (size_t)(2 * bpG + 1) * SS + s);
        }

        // Fill chunk 0
        float2 pre[8];
#pragma unroll
        for (int q = 0; q < 8; q++) {
            int i = t + 256 * q;
            int hc = i >> 10, bpl = (i >> 6) & 15, k = i & 63;
            pre[q] = __ldcg((hc ? cp : hp) + (bh * 16 + bpl) * HH + k);
        }
#pragma unroll
        for (int q = 0; q < 8; q++) {
            int i = t + 256 * q;
            int hc = i >> 10, bpl = (i >> 6) & 15, k = i & 63;
            (hc ? SC : SH)[bpl * 66 + k] = pre[q];
        }
        __syncthreads();

        unsigned long long a0 = 0, a1 = 0, a2 = 0, a3 = 0, a4 = 0;
        int buf = 0;
        for (int ch = 0; ch < 8; ch++) {
            if (ch < 7) {
#pragma unroll
                for (int q = 0; q < 8; q++) {
                    int i = t + 256 * q;
                    int hc = i >> 10, bpl = (i >> 6) & 15, k = i & 63;
                    pre[q] = __ldcg((hc ? cp : hp) +
                                    (bh * 16 + bpl) * HH + (ch + 1) * 64 + k);
                }
            }
            const float2* hrow = SH + buf * 1056 + bp * 66;
            const float2* crow = SC + buf * 1056 + bp * 66;
            const float2* w0p = SW + (0 * 8 + j7) * 514 + ch * 64;
            const float2* w1p = SW + (1 * 8 + j7) * 514 + ch * 64;
            const float2* w2p = SW + (2 * 8 + j7) * 514 + ch * 64;
            const float2* w3p = SW + (3 * 8 + j7) * 514 + ch * 64;
            const float2* w4p = SW + (4 * 8 + j7) * 514 + ch * 64;
#pragma unroll
            for (int m = 0; m < 16; m++) {
                int k = 4 * m + 2 * kh;
                ulonglong2 hv = *(const ulonglong2*)(hrow + k);
                ulonglong2 cv = *(const ulonglong2*)(crow + k);
                ulonglong2 w0 = *(const ulonglong2*)(w0p + k);
                ulonglong2 w1 = *(const ulonglong2*)(w1p + k);
                ulonglong2 w2 = *(const ulonglong2*)(w2p + k);
                ulonglong2 w3 = *(const ulonglong2*)(w3p + k);
                ulonglong2 w4 = *(const ulonglong2*)(w4p + k);
                ffma2(a0, hv.x, w0.x); ffma2(a0, hv.y, w0.y);
                ffma2(a1, hv.x, w1.x); ffma2(a1, hv.y, w1.y);
                ffma2(a2, hv.x, w2.x); ffma2(a2, hv.y, w2.y);
                ffma2(a3, hv.x, w3.x); ffma2(a3, hv.y, w3.y);
                ffma2(a4, cv.x, w4.x); ffma2(a4, cv.y, w4.y);
            }
            if (ch < 7) {
#pragma unroll
                for (int q = 0; q < 8; q++) {
                    int i = t + 256 * q;
                    int hc = i >> 10, bpl = (i >> 6) & 15, k = i & 63;
                    (hc ? SC : SH)[(buf ^ 1) * 1056 + bpl * 66 + k] = pre[q];
                }
                __syncthreads();
                buf ^= 1;
            }
        }

        // Cross-kh reduction
        __syncthreads();
        if (kh == 1) {
            unsigned long long* rr = RED + (size_t)r * 5;
            rr[0] = a0; rr[1] = a1; rr[2] = a2; rr[3] = a3; rr[4] = a4;
        }
        __syncthreads();

        if (kh == 0) {
            const unsigned long long* rr = RED + (size_t)r * 5;
            unsigned long long b0r = rr[0], b1r = rr[1], b2r = rr[2],
                               b3r = rr[3], b4r = rr[4];
            float h0n, h1n, c0n, c1n;
#pragma unroll
            for (int e = 0; e < 2; e++) {
                float pf = (e ? hi32(a0) + hi32(b0r) : lo32(a0) + lo32(b0r)) + bf + (e ? uf.y : uf.x);
                float pi = (e ? hi32(a1) + hi32(b1r) : lo32(a1) + lo32(b1r)) + bi + (e ? ui.y : ui.x);
                float po = (e ? hi32(a2) + hi32(b2r) : lo32(a2) + lo32(b2r)) + bo + (e ? uo.y : uo.x);
                float pg = (e ? hi32(a3) + hi32(b3r) : lo32(a3) + lo32(b3r)) + bg + (e ? ug.y : ug.x);
                float dd = (e ? hi32(a4) + hi32(b4r) : lo32(a4) + lo32(b4r)) + bd;

                float cs1 = tanhf(dd);
                float co = e ? cold.y : cold.x;
                float tv = e ? t1v : t0v;
                float cadj = (co - cs1) + cs1 * tv;

                float fg = sigmoidf_(pf);
                float ig = sigmoidf_(pi);
                float og = sigmoidf_(po);
                float cg = sigmoidf_(pg);

                float cnew = fg * cadj + ig * cg;
                float hnew = og * tanhf(cnew);
                if (e) { h1n = hnew; c1n = cnew; }
                else   { h0n = hnew; c0n = cnew; }
            }
            __stcg(hn + bpG * HH + j, make_float2(h0n, h1n));
            __stcg(cn + bpG * HH + j, make_float2(c0n, c1n));
            out[((size_t)(2 * bpG) * SS + s) * HH + j] = h0n;
            out[((size_t)(2 * bpG + 1) * SS + s) * HH + j] = h1n;
        }

        // Grid barrier (counting, generation = s+1)
        __syncthreads();
        if (t == 0) {
            __threadfence();
            unsigned old = atomicAdd(&g_cnt, 1);
            if (old == NBLK - 1) {
                g_cnt = 0;
                unsigned gv = (unsigned)(s + 1);
                asm volatile("st.release.gpu.global.u32 [%0], %1;"
                             :: "l"(&g_gen), "r"(gv) : "memory");
            } else {
                unsigned v;
                do {
                    asm volatile("ld.acquire.gpu.global.u32 %0, [%1];"
                                 : "=r"(v) : "l"(&g_gen) : "memory");
                } while (v < (unsigned)(s + 1));
            }
        }
        __syncthreads();
    }
}

// ---------------------------------------------------------------------------
__global__ void finalize_kernel(float* __restrict__ out) {
    int i = blockIdx.x * blockDim.x + threadIdx.x;
    if (i < BB * HH) {
        int b = i >> 9, k = i & 511;
        float2 hv = g_hp[0][(b >> 1) * HH + k];
        float2 cv = g_cp[0][(b >> 1) * HH + k];
        out[(size_t)BB * SS * HH + i] = (b & 1) ? hv.y : hv.x;
        out[(size_t)BB * SS * HH + (size_t)BB * HH + i] = (b & 1) ? cv.y : cv.x;
    }
}

// ---------------------------------------------------------------------------
extern "C" void kernel_launch(void* const* d_in, const int* in_sizes, int n_in,
                              void* d_out, int out_size) {
    const float* X      = (const float*)d_in[0];
    const float* ts     = (const float*)d_in[1];
    const float* Wall   = (const float*)d_in[2];
    const float* Wall_b = (const float*)d_in[3];
    const float* U      = (const float*)d_in[4];
    const float* Ub     = (const float*)d_in[5];
    const float* Wd     = (const float*)d_in[6];
    const float* Wdb    = (const float*)d_in[7];
    float* out = (float*)d_out;

    // Idempotent, called unconditionally (no static guards per harness rules)
    cudaFuncSetAttribute(lstm_persistent,
                         cudaFuncAttributeMaxDynamicSharedMemorySize,
                         (5 * 8 * 514 + 4 * 16 * 66) * (int)sizeof(float2));

    init_state_kernel<<<(32 * HH + 255) / 256, 256>>>();

    dim3 gu(SS * 2, FH / 128);
    u_gemm_kernel<<<gu, 256>>>(X, U, Ub);

    size_t dsm = (5 * 8 * 514 + 4 * 16 * 66) * sizeof(float2);
    lstm_persistent<<<NBLK, 256, dsm>>>(Wall, Wall_b, Wd, Wdb, ts, out);

    long long need = (long long)BB * SS * HH + 2LL * BB * HH;
    if ((long long)out_size >= need) {
        finalize_kernel<<<(BB * HH + 255) / 256, 256>>>(out);
    }
}

// round 5
// speedup vs baseline: 3.0865x; 1.6484x over previous
#include <cuda_runtime.h>
#include <cstdint>

#define BB 64
#define SS 512
#define EE 256
#define HH 512
#define FH 2048
#define NBLK 128
#define NT 256

// Global state, natural [b][k] layout
__device__ float g_hs[2][BB * HH];
__device__ float g_cs[2][BB * HH];
__device__ float g_u[(size_t)SS * BB * FH];  // [s][b][4H]
__device__ unsigned g_cnt, g_gen;

// Shared memory float offsets (step kernel)
#define SW_OFF 0
#define SW_SZ (5 * 8 * 516)             // 20640: weights [5*8 rows][516]
#define SH_OFF SW_SZ                    // [2 buf][32 b][68]
#define SC_OFF (SH_OFF + 2 * 32 * 68)   // 24992
#define SRED_OFF (SC_OFF + 2 * 32 * 68) // 29344: [8 ks][32 cell][40]
#define SM_TOTF (SRED_OFF + 8 * 32 * 40)// 39584 floats = 158336 B

// ---------------------------------------------------------------------------
__device__ __forceinline__ void ffma2(unsigned long long& d,
                                      unsigned long long a,
                                      unsigned long long b) {
    asm volatile("fma.rn.f32x2 %0, %1, %2, %0;" : "+l"(d) : "l"(a), "l"(b));
}
__device__ __forceinline__ float lo32(unsigned long long v) {
    return __uint_as_float((unsigned)(v & 0xffffffffull));
}
__device__ __forceinline__ float hi32(unsigned long long v) {
    return __uint_as_float((unsigned)(v >> 32));
}
__device__ __forceinline__ float sigmoidf_(float x) {
    return 1.0f / (1.0f + expf(-x));
}
__device__ __forceinline__ uint32_t smem_u32(const void* p) {
    uint32_t a;
    asm("{ .reg .u64 t; cvta.to.shared.u64 t, %1; cvt.u32.u64 %0, t; }"
        : "=r"(a) : "l"(p));
    return a;
}
__device__ __forceinline__ void cpasync16(uint32_t dst, const void* src) {
    asm volatile("cp.async.cg.shared.global [%0], [%1], 16;"
                 :: "r"(dst), "l"(src));
}
#define CP_COMMIT() asm volatile("cp.async.commit_group;")
#define CP_WAIT1()  asm volatile("cp.async.wait_group 1;")
#define CP_WAIT0()  asm volatile("cp.async.wait_group 0;")

// ---------------------------------------------------------------------------
__global__ void init_state_kernel() {
    int i = blockIdx.x * blockDim.x + threadIdx.x;
    if (i < BB * HH) {
        g_hs[0][i] = 0.f;
        g_cs[0][i] = 0.f;
    }
    if (i == 0) { g_cnt = 0; g_gen = 0; }
}

// ---------------------------------------------------------------------------
// u_all GEMM (batch-packed FFMA2). Output: g_u[s][b][4H].
// ---------------------------------------------------------------------------
#define UG_KC 32

__global__ __launch_bounds__(256) void u_gemm_kernel(
    const float* __restrict__ X,
    const float* __restrict__ W,
    const float* __restrict__ Bv)
{
    __shared__ float2 sA[16][UG_KC];
    __shared__ float2 sB[128][UG_KC + 2];

    int t = threadIdx.x;
    int tx = t & 15;
    int ty = t >> 4;
    int s  = blockIdx.x >> 1;
    int bh = blockIdx.x & 1;
    int b0 = bh * 32;
    int n0 = blockIdx.y * 128;

    unsigned long long acc[8];
#pragma unroll
    for (int i = 0; i < 8; i++) acc[i] = 0ull;

    for (int k0 = 0; k0 < EE; k0 += UG_KC) {
#pragma unroll
        for (int r = 0; r < 2; r++) {
            int i = t + 256 * r;
            int p = i >> 5, k = i & 31;
            int b = b0 + 2 * p;
            float x0 = X[((size_t)b * SS + s) * EE + k0 + k];
            float x1 = X[((size_t)(b + 1) * SS + s) * EE + k0 + k];
            sA[p][k] = make_float2(x0, x1);
        }
#pragma unroll
        for (int r = 0; r < 16; r++) {
            int i = t + 256 * r;
            int n = i >> 5, k = i & 31;
            float w = W[(size_t)(n0 + n) * EE + k0 + k];
            sB[n][k] = make_float2(w, w);
        }
        __syncthreads();
#pragma unroll
        for (int k = 0; k < UG_KC; k += 2) {
            unsigned long long a0 = *(const unsigned long long*)&sA[ty][k];
            unsigned long long a1 = *(const unsigned long long*)&sA[ty][k + 1];
#pragma unroll
            for (int n8 = 0; n8 < 8; n8++) {
                const unsigned long long* bp =
                    (const unsigned long long*)&sB[tx + 16 * n8][k];
                ffma2(acc[n8], a0, bp[0]);
                ffma2(acc[n8], a1, bp[1]);
            }
        }
        __syncthreads();
    }

    int p = b0 / 2 + ty;  // batch pair index; batches 2p, 2p+1
#pragma unroll
    for (int n8 = 0; n8 < 8; n8++) {
        int n = n0 + tx + 16 * n8;
        float bv = Bv[n];
        g_u[((size_t)s * BB + 2 * p) * FH + n]     = lo32(acc[n8]) + bv;
        g_u[((size_t)s * BB + 2 * p + 1) * FH + n] = hi32(acc[n8]) + bv;
    }
}

// ---------------------------------------------------------------------------
// Persistent recurrence. 128 blocks = 64 j-tiles(8) x 2 batch-halves(32).
// Thread t: ks = t>>5 (k-slice warp), jg = (t>>3)&3, bg = t&7.
// Per thread: Mb=4 batches (bg+8*bi), Nb=2 j (jg*2+ji), 5 dots, k-packed.
// Weights (unduplicated) resident in smem for all 512 steps.
// ---------------------------------------------------------------------------
__global__ __launch_bounds__(NT, 1) void lstm_persistent(
    const float* __restrict__ Wall,
    const float* __restrict__ Wall_b,
    const float* __restrict__ Wd,
    const float* __restrict__ Wd_b,
    const float* __restrict__ ts,
    float* __restrict__ out)
{
    extern __shared__ float sm[];
    const uint32_t smb = smem_u32(sm);

    const int t  = threadIdx.x;
    const int ks = t >> 5;
    const int jg = (t >> 3) & 3;
    const int bg = t & 7;
    const int jt = blockIdx.x >> 1;
    const int bh = blockIdx.x & 1;
    const int j0 = jt * 8;

    // Epilogue identity: eb = t>>3 (0..31 local batch), ejl = t&7 (local j)
    const int eb  = t >> 3;
    const int ejl = t & 7;
    const int ej  = j0 + ejl;
    const int ebg = bh * 32 + eb;

    // One-time weight slice load: rows [g*8 + jl], k 0..511, stride 516
#pragma unroll 4
    for (int it = 0; it < 80; it++) {
        int i = t + NT * it;
        int g = i >> 12;
        int jl = (i >> 9) & 7;
        int k = i & 511;
        float w = (g < 4) ? Wall[(size_t)(g * HH + j0 + jl) * HH + k]
                          : Wd[(size_t)(j0 + jl) * HH + k];
        sm[SW_OFF + (g * 8 + jl) * 516 + k] = w;
    }
    const float zbf = Wall_b[ej];
    const float zbi = Wall_b[HH + ej];
    const float zbo = Wall_b[2 * HH + ej];
    const float zbg = Wall_b[3 * HH + ej];
    const float zbd = Wd_b[ej];
    __syncthreads();

    for (int s = 0; s < SS; s++) {
        const int par = s & 1;
        const float* hp = g_hs[par];
        const float* cp = g_cs[par];
        float* hn = g_hs[par ^ 1];
        float* cn = g_cs[par ^ 1];

        // Epilogue operand prefetch (arrives under the k-loop)
        const float* ub = g_u + ((size_t)s * BB + ebg) * FH;
        float uf = __ldcs(ub + ej);
        float ui = __ldcs(ub + HH + ej);
        float uo = __ldcs(ub + 2 * HH + ej);
        float ug = __ldcs(ub + 3 * HH + ej);
        float cold = __ldcg(cp + (size_t)ebg * HH + ej);
        float tsv = __ldg(ts + (size_t)ebg * SS + s);

        unsigned long long acc[5][2][4];
#pragma unroll
        for (int g = 0; g < 5; g++)
#pragma unroll
            for (int ji = 0; ji < 2; ji++)
#pragma unroll
                for (int bi = 0; bi < 4; bi++) acc[g][ji][bi] = 0ull;

        // Stage chunk 0 (h+c, 8KB each): i -> k4 = i&15, b = i>>4
#pragma unroll
        for (int q = 0; q < 2; q++) {
            int i = t + NT * q;
            int k4 = i & 15, b = i >> 4;
            const float* sh_ = hp + (size_t)(bh * 32 + b) * HH + k4 * 4;
            const float* sc_ = cp + (size_t)(bh * 32 + b) * HH + k4 * 4;
            cpasync16(smb + (uint32_t)((SH_OFF + b * 68 + k4 * 4) * 4), sh_);
            cpasync16(smb + (uint32_t)((SC_OFF + b * 68 + k4 * 4) * 4), sc_);
        }
        CP_COMMIT();

        int buf = 0;
#pragma unroll 1
        for (int ch = 0; ch < 8; ch++) {
            if (ch < 7) {
#pragma unroll
                for (int q = 0; q < 2; q++) {
                    int i = t + NT * q;
                    int k4 = i & 15, b = i >> 4;
                    const float* sh_ = hp + (size_t)(bh * 32 + b) * HH +
                                       (ch + 1) * 64 + k4 * 4;
                    const float* sc_ = cp + (size_t)(bh * 32 + b) * HH +
                                       (ch + 1) * 64 + k4 * 4;
                    int bo = (buf ^ 1) * 2176 + b * 68 + k4 * 4;
                    cpasync16(smb + (uint32_t)((SH_OFF + bo) * 4), sh_);
                    cpasync16(smb + (uint32_t)((SC_OFF + bo) * 4), sc_);
                }
                CP_COMMIT();
                CP_WAIT1();
            } else {
                CP_WAIT0();
            }
            __syncthreads();

            // Load this thread's state: 4 batches x 8 k (2 float4 each)
            ulonglong2 hv[4][2], cv[4][2];
#pragma unroll
            for (int bi = 0; bi < 4; bi++) {
                const float* hq = sm + SH_OFF + buf * 2176 +
                                  (bg + 8 * bi) * 68 + ks * 8;
                const float* cq = sm + SC_OFF + buf * 2176 +
                                  (bg + 8 * bi) * 68 + ks * 8;
                hv[bi][0] = *(const ulonglong2*)hq;
                hv[bi][1] = *(const ulonglong2*)(hq + 4);
                cv[bi][0] = *(const ulonglong2*)cq;
                cv[bi][1] = *(const ulonglong2*)(cq + 4);
            }
            // Weights loaded once per (g, ji), reused across 4 batches
#pragma unroll
            for (int g = 0; g < 5; g++) {
#pragma unroll
                for (int ji = 0; ji < 2; ji++) {
                    const float* wp = sm + SW_OFF +
                        (g * 8 + jg * 2 + ji) * 516 + ch * 64 + ks * 8;
                    ulonglong2 w0 = *(const ulonglong2*)wp;
                    ulonglong2 w1 = *(const ulonglong2*)(wp + 4);
                    if (g < 4) {
#pragma unroll
                        for (int bi = 0; bi < 4; bi++) {
                            ffma2(acc[g][ji][bi], hv[bi][0].x, w0.x);
                            ffma2(acc[g][ji][bi], hv[bi][0].y, w0.y);
                            ffma2(acc[g][ji][bi], hv[bi][1].x, w1.x);
                            ffma2(acc[g][ji][bi], hv[bi][1].y, w1.y);
                        }
                    } else {
#pragma unroll
                        for (int bi = 0; bi < 4; bi++) {
                            ffma2(acc[g][ji][bi], cv[bi][0].x, w0.x);
                            ffma2(acc[g][ji][bi], cv[bi][0].y, w0.y);
                            ffma2(acc[g][ji][bi], cv[bi][1].x, w1.x);
                            ffma2(acc[g][ji][bi], cv[bi][1].y, w1.y);
                        }
                    }
                }
            }
            __syncthreads();
            buf ^= 1;
        }

        // Partial-sum scatter: fold f32x2, write [ks][jg*8+bg][g*8+ji*4+bi]
        {
            float* R = sm + SRED_OFF + ks * 1280 + (t & 31) * 40;
#pragma unroll
            for (int g = 0; g < 5; g++)
#pragma unroll
                for (int ji = 0; ji < 2; ji++)
#pragma unroll
                    for (int bi = 0; bi < 4; bi++)
                        R[g * 8 + ji * 4 + bi] =
                            lo32(acc[g][ji][bi]) + hi32(acc[g][ji][bi]);
        }
        __syncthreads();

        // Gather across 8 k-slices for (ej, eb) and run the gate epilogue
        {
            int cellS = (ejl >> 1) * 8 + (eb & 7);
            int idxb = (ejl & 1) * 4 + (eb >> 3);
            float sum0 = 0.f, sum1 = 0.f, sum2 = 0.f, sum3 = 0.f, sum4 = 0.f;
#pragma unroll
            for (int k2 = 0; k2 < 8; k2++) {
                const float* R = sm + SRED_OFF + k2 * 1280 + cellS * 40 + idxb;
                sum0 += R[0];
                sum1 += R[8];
                sum2 += R[16];
                sum3 += R[24];
                sum4 += R[32];
            }
            float pf = sum0 + zbf + uf;
            float pi = sum1 + zbi + ui;
            float po = sum2 + zbo + uo;
            float pg = sum3 + zbg + ug;
            float dd = sum4 + zbd;

            float cs1 = tanhf(dd);
            float cadj = (cold - cs1) + cs1 * tsv;
            float fg = sigmoidf_(pf);
            float ig = sigmoidf_(pi);
            float og = sigmoidf_(po);
            float cg = sigmoidf_(pg);
            float cnew = fg * cadj + ig * cg;
            float hnew = og * tanhf(cnew);

            __stcg(hn + (size_t)ebg * HH + ej, hnew);
            __stcg(cn + (size_t)ebg * HH + ej, cnew);
            out[((size_t)ebg * SS + s) * HH + ej] = hnew;
        }

        // Grid barrier
        __syncthreads();
        if (t == 0) {
            __threadfence();
            unsigned old = atomicAdd(&g_cnt, 1);
            if (old == NBLK - 1) {
                g_cnt = 0;
                unsigned gv = (unsigned)(s + 1);
                asm volatile("st.release.gpu.global.u32 [%0], %1;"
                             :: "l"(&g_gen), "r"(gv) : "memory");
            } else {
                unsigned v;
                do {
                    asm volatile("ld.acquire.gpu.global.u32 %0, [%1];"
                                 : "=r"(v) : "l"(&g_gen) : "memory");
                } while (v < (unsigned)(s + 1));
            }
        }
        __syncthreads();
    }
}

// ---------------------------------------------------------------------------
__global__ void finalize_kernel(float* __restrict__ out) {
    int i = blockIdx.x * blockDim.x + threadIdx.x;
    if (i < BB * HH) {
        out[(size_t)BB * SS * HH + i] = g_hs[0][i];
        out[(size_t)BB * SS * HH + (size_t)BB * HH + i] = g_cs[0][i];
    }
}

// ---------------------------------------------------------------------------
extern "C" void kernel_launch(void* const* d_in, const int* in_sizes, int n_in,
                              void* d_out, int out_size) {
    const float* X      = (const float*)d_in[0];
    const float* ts     = (const float*)d_in[1];
    const float* Wall   = (const float*)d_in[2];
    const float* Wall_b = (const float*)d_in[3];
    const float* U      = (const float*)d_in[4];
    const float* Ub     = (const float*)d_in[5];
    const float* Wd     = (const float*)d_in[6];
    const float* Wdb    = (const float*)d_in[7];
    float* out = (float*)d_out;

    cudaFuncSetAttribute(lstm_persistent,
                         cudaFuncAttributeMaxDynamicSharedMemorySize,
                         SM_TOTF * (int)sizeof(float));

    init_state_kernel<<<(BB * HH + 255) / 256, 256>>>();

    dim3 gu(SS * 2, FH / 128);
    u_gemm_kernel<<<gu, 256>>>(X, U, Ub);

    lstm_persistent<<<NBLK, NT, SM_TOTF * sizeof(float)>>>(
        Wall, Wall_b, Wd, Wdb, ts, out);

    long long need = (long long)BB * SS * HH + 2LL * BB * HH;
    if ((long long)out_size >= need) {
        finalize_kernel<<<(BB * HH + 255) / 256, 256>>>(out);
    }
}

// round 6
// speedup vs baseline: 3.1544x; 1.0220x over previous
#include <cuda_runtime.h>
#include <cstdint>

#define BB 64
#define SS 512
#define EE 256
#define HH 512
#define FH 2048
#define NBLK 128
#define NT 256

__device__ float g_hs[2][BB * HH];
__device__ float g_cs[2][BB * HH];
__device__ float g_u[(size_t)SS * BB * FH];  // [s][b][4H]
__device__ unsigned g_cnt, g_gen;

// Shared memory float offsets (step kernel)
#define SW_OFF 0
#define SW_SZ (5 * 8 * 516)               // 20640 weights [40 rows][516]
#define SH_OFF SW_SZ                      // [2 buf][32 b][132]
#define SC_OFF (SH_OFF + 2 * 32 * 132)    // +8448
#define SRED_OFF (SC_OFF + 2 * 32 * 132)  // +8448 -> [8 ks][40 slot][32 cell]
#define SM_TOTF (SRED_OFF + 8 * 40 * 32)  // +10240 = 47776 floats = 191104 B

// ---------------------------------------------------------------------------
__device__ __forceinline__ void ffma2(unsigned long long& d,
                                      unsigned long long a,
                                      unsigned long long b) {
    asm volatile("fma.rn.f32x2 %0, %1, %2, %0;" : "+l"(d) : "l"(a), "l"(b));
}
__device__ __forceinline__ float lo32(unsigned long long v) {
    return __uint_as_float((unsigned)(v & 0xffffffffull));
}
__device__ __forceinline__ float hi32(unsigned long long v) {
    return __uint_as_float((unsigned)(v >> 32));
}
__device__ __forceinline__ float tanha(float x) {
    float y;
    asm("tanh.approx.f32 %0, %1;" : "=f"(y) : "f"(x));
    return y;
}
__device__ __forceinline__ float sigm(float x) {
    return 0.5f * tanha(0.5f * x) + 0.5f;
}
__device__ __forceinline__ uint32_t smem_u32(const void* p) {
    uint32_t a;
    asm("{ .reg .u64 t; cvta.to.shared.u64 t, %1; cvt.u32.u64 %0, t; }"
        : "=r"(a) : "l"(p));
    return a;
}
__device__ __forceinline__ void cpasync16(uint32_t dst, const void* src) {
    asm volatile("cp.async.cg.shared.global [%0], [%1], 16;"
                 :: "r"(dst), "l"(src));
}
#define CP_COMMIT() asm volatile("cp.async.commit_group;")
#define CP_WAIT1()  asm volatile("cp.async.wait_group 1;")
#define CP_WAIT0()  asm volatile("cp.async.wait_group 0;")

// ---------------------------------------------------------------------------
__global__ void init_state_kernel() {
    int i = blockIdx.x * blockDim.x + threadIdx.x;
    if (i < BB * HH) {
        g_hs[0][i] = 0.f;
        g_cs[0][i] = 0.f;
    }
    if (i == 0) { g_cnt = 0; g_gen = 0; }
}

// ---------------------------------------------------------------------------
// u_all GEMM (batch-packed FFMA2). Output: g_u[s][b][4H].
// ---------------------------------------------------------------------------
#define UG_KC 32

__global__ __launch_bounds__(256) void u_gemm_kernel(
    const float* __restrict__ X,
    const float* __restrict__ W,
    const float* __restrict__ Bv)
{
    __shared__ float2 sA[16][UG_KC];
    __shared__ float2 sB[128][UG_KC + 2];

    int t = threadIdx.x;
    int tx = t & 15;
    int ty = t >> 4;
    int s  = blockIdx.x >> 1;
    int bh = blockIdx.x & 1;
    int b0 = bh * 32;
    int n0 = blockIdx.y * 128;

    unsigned long long acc[8];
#pragma unroll
    for (int i = 0; i < 8; i++) acc[i] = 0ull;

    for (int k0 = 0; k0 < EE; k0 += UG_KC) {
#pragma unroll
        for (int r = 0; r < 2; r++) {
            int i = t + 256 * r;
            int p = i >> 5, k = i & 31;
            int b = b0 + 2 * p;
            float x0 = X[((size_t)b * SS + s) * EE + k0 + k];
            float x1 = X[((size_t)(b + 1) * SS + s) * EE + k0 + k];
            sA[p][k] = make_float2(x0, x1);
        }
#pragma unroll
        for (int r = 0; r < 16; r++) {
            int i = t + 256 * r;
            int n = i >> 5, k = i & 31;
            float w = W[(size_t)(n0 + n) * EE + k0 + k];
            sB[n][k] = make_float2(w, w);
        }
        __syncthreads();
#pragma unroll
        for (int k = 0; k < UG_KC; k += 2) {
            unsigned long long a0 = *(const unsigned long long*)&sA[ty][k];
            unsigned long long a1 = *(const unsigned long long*)&sA[ty][k + 1];
#pragma unroll
            for (int n8 = 0; n8 < 8; n8++) {
                const unsigned long long* bp =
                    (const unsigned long long*)&sB[tx + 16 * n8][k];
                ffma2(acc[n8], a0, bp[0]);
                ffma2(acc[n8], a1, bp[1]);
            }
        }
        __syncthreads();
    }

    int p = b0 / 2 + ty;
#pragma unroll
    for (int n8 = 0; n8 < 8; n8++) {
        int n = n0 + tx + 16 * n8;
        float bv = Bv[n];
        g_u[((size_t)s * BB + 2 * p) * FH + n]     = lo32(acc[n8]) + bv;
        g_u[((size_t)s * BB + 2 * p + 1) * FH + n] = hi32(acc[n8]) + bv;
    }
}

// ---------------------------------------------------------------------------
// Persistent recurrence. 128 blocks = 64 j-tiles(8) x 2 batch-halves(32).
// Thread t: ks = t>>5, jg = (t>>3)&3, bg = t&7. Mb=4 batches, Nb=2 j.
// 4 double-buffered chunks of 128 k; weights smem-resident for all steps.
// ---------------------------------------------------------------------------
__global__ __launch_bounds__(NT, 1) void lstm_persistent(
    const float* __restrict__ Wall,
    const float* __restrict__ Wall_b,
    const float* __restrict__ Wd,
    const float* __restrict__ Wd_b,
    const float* __restrict__ ts,
    float* __restrict__ out)
{
    extern __shared__ float sm[];
    const uint32_t smb = smem_u32(sm);

    const int t  = threadIdx.x;
    const int ks = t >> 5;
    const int jg = (t >> 3) & 3;
    const int bg = t & 7;
    const int jt = blockIdx.x >> 1;
    const int bh = blockIdx.x & 1;
    const int j0 = jt * 8;

    // Epilogue identity
    const int eb  = t >> 3;
    const int ejl = t & 7;
    const int ej  = j0 + ejl;
    const int ebg = bh * 32 + eb;
    const int cell = (ejl >> 1) * 8 + (eb & 7);
    const int idxb = (ejl & 1) * 4 + (eb >> 3);

    // One-time weight slice load: rows [g*8+jl][516]
#pragma unroll 4
    for (int it = 0; it < 80; it++) {
        int i = t + NT * it;
        int g = i >> 12;
        int jl = (i >> 9) & 7;
        int k = i & 511;
        float w = (g < 4) ? Wall[(size_t)(g * HH + j0 + jl) * HH + k]
                          : Wd[(size_t)(j0 + jl) * HH + k];
        sm[SW_OFF + (g * 8 + jl) * 516 + k] = w;
    }
    const float zbf = Wall_b[ej];
    const float zbi = Wall_b[HH + ej];
    const float zbo = Wall_b[2 * HH + ej];
    const float zbg = Wall_b[3 * HH + ej];
    const float zbd = Wd_b[ej];
    __syncthreads();

    for (int s = 0; s < SS; s++) {
        const int par = s & 1;
        const float* hp = g_hs[par];
        const float* cp = g_cs[par];
        float* hn = g_hs[par ^ 1];
        float* cn = g_cs[par ^ 1];

        // Epilogue operand prefetch (arrives under the k-loop)
        const float* ub = g_u + ((size_t)s * BB + ebg) * FH;
        float uf = __ldcs(ub + ej);
        float ui = __ldcs(ub + HH + ej);
        float uo = __ldcs(ub + 2 * HH + ej);
        float ug = __ldcs(ub + 3 * HH + ej);
        float cold = __ldcg(cp + (size_t)ebg * HH + ej);
        float tsv = __ldg(ts + (size_t)ebg * SS + s);

        unsigned long long acc[5][2][4];
#pragma unroll
        for (int g = 0; g < 5; g++)
#pragma unroll
            for (int ji = 0; ji < 2; ji++)
#pragma unroll
                for (int bi = 0; bi < 4; bi++) acc[g][ji][bi] = 0ull;

        // Stage chunk 0 (128 k): i -> k4 = i&31, b = i>>5
#pragma unroll
        for (int q = 0; q < 4; q++) {
            int i = t + NT * q;
            int k4 = i & 31, b = i >> 5;
            const float* sh_ = hp + (size_t)(bh * 32 + b) * HH + k4 * 4;
            const float* sc_ = cp + (size_t)(bh * 32 + b) * HH + k4 * 4;
            cpasync16(smb + (uint32_t)((SH_OFF + b * 132 + k4 * 4) * 4), sh_);
            cpasync16(smb + (uint32_t)((SC_OFF + b * 132 + k4 * 4) * 4), sc_);
        }
        CP_COMMIT();

        int buf = 0;
#pragma unroll 1
        for (int ch = 0; ch < 4; ch++) {
            if (ch < 3) {
#pragma unroll
                for (int q = 0; q < 4; q++) {
                    int i = t + NT * q;
                    int k4 = i & 31, b = i >> 5;
                    const float* sh_ = hp + (size_t)(bh * 32 + b) * HH +
                                       (ch + 1) * 128 + k4 * 4;
                    const float* sc_ = cp + (size_t)(bh * 32 + b) * HH +
                                       (ch + 1) * 128 + k4 * 4;
                    int bo = (buf ^ 1) * 4224 + b * 132 + k4 * 4;
                    cpasync16(smb + (uint32_t)((SH_OFF + bo) * 4), sh_);
                    cpasync16(smb + (uint32_t)((SC_OFF + bo) * 4), sc_);
                }
                CP_COMMIT();
                CP_WAIT1();
            } else {
                CP_WAIT0();
            }
            __syncthreads();

#pragma unroll
            for (int hf = 0; hf < 2; hf++) {
                // State: 4 batches x 8 k (2 float4 each)
                ulonglong2 hv[4][2], cv[4][2];
#pragma unroll
                for (int bi = 0; bi < 4; bi++) {
                    const float* hq = sm + SH_OFF + buf * 4224 +
                                      (bg + 8 * bi) * 132 + hf * 64 + ks * 8;
                    const float* cq = sm + SC_OFF + buf * 4224 +
                                      (bg + 8 * bi) * 132 + hf * 64 + ks * 8;
                    hv[bi][0] = *(const ulonglong2*)hq;
                    hv[bi][1] = *(const ulonglong2*)(hq + 4);
                    cv[bi][0] = *(const ulonglong2*)cq;
                    cv[bi][1] = *(const ulonglong2*)(cq + 4);
                }
#pragma unroll
                for (int g = 0; g < 5; g++) {
#pragma unroll
                    for (int ji = 0; ji < 2; ji++) {
                        const float* wp = sm + SW_OFF +
                            (g * 8 + jg * 2 + ji) * 516 +
                            ch * 128 + hf * 64 + ks * 8;
                        ulonglong2 w0 = *(const ulonglong2*)wp;
                        ulonglong2 w1 = *(const ulonglong2*)(wp + 4);
                        if (g < 4) {
#pragma unroll
                            for (int bi = 0; bi < 4; bi++) {
                                ffma2(acc[g][ji][bi], hv[bi][0].x, w0.x);
                                ffma2(acc[g][ji][bi], hv[bi][0].y, w0.y);
                                ffma2(acc[g][ji][bi], hv[bi][1].x, w1.x);
                                ffma2(acc[g][ji][bi], hv[bi][1].y, w1.y);
                            }
                        } else {
#pragma unroll
                            for (int bi = 0; bi < 4; bi++) {
                                ffma2(acc[g][ji][bi], cv[bi][0].x, w0.x);
                                ffma2(acc[g][ji][bi], cv[bi][0].y, w0.y);
                                ffma2(acc[g][ji][bi], cv[bi][1].x, w1.x);
                                ffma2(acc[g][ji][bi], cv[bi][1].y, w1.y);
                            }
                        }
                    }
                }
            }
            __syncthreads();
            buf ^= 1;
        }

        // Partial scatter: R[ks][slot][cell], lanes=cells -> conflict-free
        {
            float* R = sm + SRED_OFF + ks * 1280 + (t & 31);
#pragma unroll
            for (int g = 0; g < 5; g++)
#pragma unroll
                for (int ji = 0; ji < 2; ji++)
#pragma unroll
                    for (int bi = 0; bi < 4; bi++)
                        R[(g * 8 + ji * 4 + bi) * 32] =
                            lo32(acc[g][ji][bi]) + hi32(acc[g][ji][bi]);
        }
        __syncthreads();

        // Gather across 8 k-slices + gate epilogue
        {
            float sum0 = 0.f, sum1 = 0.f, sum2 = 0.f, sum3 = 0.f, sum4 = 0.f;
#pragma unroll
            for (int k2 = 0; k2 < 8; k2++) {
                const float* R = sm + SRED_OFF + k2 * 1280 + idxb * 32 + cell;
                sum0 += R[0 * 256];
                sum1 += R[1 * 256];
                sum2 += R[2 * 256];
                sum3 += R[3 * 256];
                sum4 += R[4 * 256];
            }
            float pf = sum0 + zbf + uf;
            float pi = sum1 + zbi + ui;
            float po = sum2 + zbo + uo;
            float pg = sum3 + zbg + ug;
            float dd = sum4 + zbd;

            float cs1 = tanha(dd);
            float cadj = (cold - cs1) + cs1 * tsv;
            float fg = sigm(pf);
            float ig = sigm(pi);
            float og = sigm(po);
            float cg = sigm(pg);
            float cnew = fg * cadj + ig * cg;
            float hnew = og * tanha(cnew);

            __stcg(hn + (size_t)ebg * HH + ej, hnew);
            __stcg(cn + (size_t)ebg * HH + ej, cnew);
            out[((size_t)ebg * SS + s) * HH + ej] = hnew;
        }

        // Grid barrier
        __syncthreads();
        if (t == 0) {
            __threadfence();
            unsigned old = atomicAdd(&g_cnt, 1);
            if (old == NBLK - 1) {
                g_cnt = 0;
                unsigned gv = (unsigned)(s + 1);
                asm volatile("st.release.gpu.global.u32 [%0], %1;"
                             :: "l"(&g_gen), "r"(gv) : "memory");
            } else {
                unsigned v;
                do {
                    asm volatile("ld.acquire.gpu.global.u32 %0, [%1];"
                                 : "=r"(v) : "l"(&g_gen) : "memory");
                } while (v < (unsigned)(s + 1));
            }
        }
        __syncthreads();
    }
}

// ---------------------------------------------------------------------------
__global__ void finalize_kernel(float* __restrict__ out) {
    int i = blockIdx.x * blockDim.x + threadIdx.x;
    if (i < BB * HH) {
        out[(size_t)BB * SS * HH + i] = g_hs[0][i];
        out[(size_t)BB * SS * HH + (size_t)BB * HH + i] = g_cs[0][i];
    }
}

// ---------------------------------------------------------------------------
extern "C" void kernel_launch(void* const* d_in, const int* in_sizes, int n_in,
                              void* d_out, int out_size) {
    const float* X      = (const float*)d_in[0];
    const float* ts     = (const float*)d_in[1];
    const float* Wall   = (const float*)d_in[2];
    const float* Wall_b = (const float*)d_in[3];
    const float* U      = (const float*)d_in[4];
    const float* Ub     = (const float*)d_in[5];
    const float* Wd     = (const float*)d_in[6];
    const float* Wdb    = (const float*)d_in[7];
    float* out = (float*)d_out;

    cudaFuncSetAttribute(lstm_persistent,
                         cudaFuncAttributeMaxDynamicSharedMemorySize,
                         SM_TOTF * (int)sizeof(float));

    init_state_kernel<<<(BB * HH + 255) / 256, 256>>>();

    dim3 gu(SS * 2, FH / 128);
    u_gemm_kernel<<<gu, 256>>>(X, U, Ub);

    lstm_persistent<<<NBLK, NT, SM_TOTF * sizeof(float)>>>(
        Wall, Wall_b, Wd, Wdb, ts, out);

    long long need = (long long)BB * SS * HH + 2LL * BB * HH;
    if ((long long)out_size >= need) {
        finalize_kernel<<<(BB * HH + 255) / 256, 256>>>(out);
    }
}

// round 8
// speedup vs baseline: 3.1987x; 1.0141x over previous
#include <cuda_runtime.h>
#include <cstdint>

#define BB 64
#define SS 512
#define EE 256
#define HH 512
#define FH 2048
#define NBLK 128
#define NT 256

__device__ float g_hs[2][BB * HH];
__device__ float g_cs[2][BB * HH];
__device__ float g_u[(size_t)SS * BB * FH];  // [s][b][4H]
__device__ unsigned g_cnt, g_gen;

// Shared memory float offsets (persistent kernel)
#define SW_OFF 0
#define SW_SZ (5 * 8 * 516)             // 20640: weights [40 rows][516]
#define SH_OFF SW_SZ                    // h state [32 b][516]
#define SC_OFF (SH_OFF + 32 * 516)      // c state [32 b][516]
#define SRED_OFF SH_OFF                 // reduction ALIASES state (post-compute)
#define SM_TOTF (SC_OFF + 32 * 516)     // 53664 floats = 214656 B

// ---------------------------------------------------------------------------
__device__ __forceinline__ void ffma2(unsigned long long& d,
                                      unsigned long long a,
                                      unsigned long long b) {
    asm volatile("fma.rn.f32x2 %0, %1, %2, %0;" : "+l"(d) : "l"(a), "l"(b));
}
__device__ __forceinline__ float lo32(unsigned long long v) {
    return __uint_as_float((unsigned)(v & 0xffffffffull));
}
__device__ __forceinline__ float hi32(unsigned long long v) {
    return __uint_as_float((unsigned)(v >> 32));
}
__device__ __forceinline__ float tanha(float x) {
    float y;
    asm("tanh.approx.f32 %0, %1;" : "=f"(y) : "f"(x));
    return y;
}
__device__ __forceinline__ float sigm(float x) {
    return 0.5f * tanha(0.5f * x) + 0.5f;
}
__device__ __forceinline__ uint32_t smem_u32(const void* p) {
    uint32_t a;
    asm("{ .reg .u64 t; cvta.to.shared.u64 t, %1; cvt.u32.u64 %0, t; }"
        : "=r"(a) : "l"(p));
    return a;
}
__device__ __forceinline__ void cpasync16(uint32_t dst, const void* src) {
    asm volatile("cp.async.cg.shared.global [%0], [%1], 16;"
                 :: "r"(dst), "l"(src));
}
#define CP_COMMIT() asm volatile("cp.async.commit_group;")
#define CP_WAIT(n)  asm volatile("cp.async.wait_group %0;" :: "n"(n))

// ---------------------------------------------------------------------------
__global__ void init_state_kernel() {
    int i = blockIdx.x * blockDim.x + threadIdx.x;
    if (i < BB * HH) {
        g_hs[0][i] = 0.f;
        g_cs[0][i] = 0.f;
    }
    if (i == 0) { g_cnt = 0; g_gen = 0; }
}

// ---------------------------------------------------------------------------
// u_all GEMM (batch-packed FFMA2). Output: g_u[s][b][4H].
// ---------------------------------------------------------------------------
#define UG_KC 32

__global__ __launch_bounds__(256) void u_gemm_kernel(
    const float* __restrict__ X,
    const float* __restrict__ W,
    const float* __restrict__ Bv)
{
    __shared__ float2 sA[16][UG_KC];
    __shared__ float2 sB[128][UG_KC + 2];

    int t = threadIdx.x;
    int tx = t & 15;
    int ty = t >> 4;
    int s  = blockIdx.x >> 1;
    int bh = blockIdx.x & 1;
    int b0 = bh * 32;
    int n0 = blockIdx.y * 128;

    unsigned long long acc[8];
#pragma unroll
    for (int i = 0; i < 8; i++) acc[i] = 0ull;

    for (int k0 = 0; k0 < EE; k0 += UG_KC) {
#pragma unroll
        for (int r = 0; r < 2; r++) {
            int i = t + 256 * r;
            int p = i >> 5, k = i & 31;
            int b = b0 + 2 * p;
            float x0 = X[((size_t)b * SS + s) * EE + k0 + k];
            float x1 = X[((size_t)(b + 1) * SS + s) * EE + k0 + k];
            sA[p][k] = make_float2(x0, x1);
        }
#pragma unroll
        for (int r = 0; r < 16; r++) {
            int i = t + 256 * r;
            int n = i >> 5, k = i & 31;
            float w = W[(size_t)(n0 + n) * EE + k0 + k];
            sB[n][k] = make_float2(w, w);
        }
        __syncthreads();
#pragma unroll
        for (int k = 0; k < UG_KC; k += 2) {
            unsigned long long a0 = *(const unsigned long long*)&sA[ty][k];
            unsigned long long a1 = *(const unsigned long long*)&sA[ty][k + 1];
#pragma unroll
            for (int n8 = 0; n8 < 8; n8++) {
                const unsigned long long* bp =
                    (const unsigned long long*)&sB[tx + 16 * n8][k];
                ffma2(acc[n8], a0, bp[0]);
                ffma2(acc[n8], a1, bp[1]);
            }
        }
        __syncthreads();
    }

    int p = b0 / 2 + ty;
#pragma unroll
    for (int n8 = 0; n8 < 8; n8++) {
        int n = n0 + tx + 16 * n8;
        float bv = Bv[n];
        g_u[((size_t)s * BB + 2 * p) * FH + n]     = lo32(acc[n8]) + bv;
        g_u[((size_t)s * BB + 2 * p + 1) * FH + n] = hi32(acc[n8]) + bv;
    }
}

// ---------------------------------------------------------------------------
// Persistent recurrence. 128 blocks = 64 j-tiles(8) x 2 batch-halves(32).
// Thread t: ks = t>>5, jg = (t>>3)&3, bg = t&7. Mb=4 batches, Nb=2 j.
// Whole state staged at step start (4 cp.async groups, one per 128-k chunk);
// weights smem-resident for all 512 steps; final h/c tail written in-kernel.
// ---------------------------------------------------------------------------
__global__ __launch_bounds__(NT, 1) void lstm_persistent(
    const float* __restrict__ Wall,
    const float* __restrict__ Wall_b,
    const float* __restrict__ Wd,
    const float* __restrict__ Wd_b,
    const float* __restrict__ ts,
    float* __restrict__ out,
    int write_tail)
{
    extern __shared__ float sm[];
    const uint32_t smb = smem_u32(sm);

    const int t  = threadIdx.x;
    const int ks = t >> 5;
    const int jg = (t >> 3) & 3;
    const int bg = t & 7;
    const int jt = blockIdx.x >> 1;
    const int bh = blockIdx.x & 1;
    const int j0 = jt * 8;

    // Epilogue identity
    const int eb  = t >> 3;
    const int ejl = t & 7;
    const int ej  = j0 + ejl;
    const int ebg = bh * 32 + eb;
    const int cell = (ejl >> 1) * 8 + (eb & 7);
    const int idxb = (ejl & 1) * 4 + (eb >> 3);

    // One-time weight slice load: rows [g*8+jl][516]
#pragma unroll 4
    for (int it = 0; it < 80; it++) {
        int i = t + NT * it;
        int g = i >> 12;
        int jl = (i >> 9) & 7;
        int k = i & 511;
        float w = (g < 4) ? Wall[(size_t)(g * HH + j0 + jl) * HH + k]
                          : Wd[(size_t)(j0 + jl) * HH + k];
        sm[SW_OFF + (g * 8 + jl) * 516 + k] = w;
    }
    const float zbf = Wall_b[ej];
    const float zbi = Wall_b[HH + ej];
    const float zbo = Wall_b[2 * HH + ej];
    const float zbg = Wall_b[3 * HH + ej];
    const float zbd = Wd_b[ej];
    __syncthreads();

    for (int s = 0; s < SS; s++) {
        const int par = s & 1;
        const float* hp = g_hs[par];
        const float* cp = g_cs[par];
        float* hn = g_hs[par ^ 1];
        float* cn = g_cs[par ^ 1];

        // Epilogue operand prefetch (arrives under the k-loop)
        const float* ub = g_u + ((size_t)s * BB + ebg) * FH;
        float uf = __ldcs(ub + ej);
        float ui = __ldcs(ub + HH + ej);
        float uo = __ldcs(ub + 2 * HH + ej);
        float ug = __ldcs(ub + 3 * HH + ej);
        float cold = __ldcg(cp + (size_t)ebg * HH + ej);
        float tsv = __ldg(ts + (size_t)ebg * SS + s);

        // Issue ALL state staging up-front: 4 groups (one per 128-k chunk)
#pragma unroll
        for (int ch = 0; ch < 4; ch++) {
#pragma unroll
            for (int q = 0; q < 8; q++) {
                int o = t + NT * (q & 3);
                int b = o >> 5;          // 0..31
                int k4 = o & 31;         // 0..31 (x4 floats)
                int koff = ch * 128 + k4 * 4;
                if (q < 4) {
                    cpasync16(smb + (uint32_t)((SH_OFF + b * 516 + koff) * 4),
                              hp + (size_t)(bh * 32 + b) * HH + koff);
                } else {
                    cpasync16(smb + (uint32_t)((SC_OFF + b * 516 + koff) * 4),
                              cp + (size_t)(bh * 32 + b) * HH + koff);
                }
            }
            CP_COMMIT();
        }

        unsigned long long acc[5][2][4];
#pragma unroll
        for (int g = 0; g < 5; g++)
#pragma unroll
            for (int ji = 0; ji < 2; ji++)
#pragma unroll
                for (int bi = 0; bi < 4; bi++) acc[g][ji][bi] = 0ull;

#pragma unroll 1
        for (int ch = 0; ch < 4; ch++) {
            switch (ch) {
                case 0: CP_WAIT(3); break;
                case 1: CP_WAIT(2); break;
                case 2: CP_WAIT(1); break;
                default: CP_WAIT(0); break;
            }
            __syncthreads();

#pragma unroll
            for (int hf = 0; hf < 2; hf++) {
                ulonglong2 hv[4][2], cv[4][2];
#pragma unroll
                for (int bi = 0; bi < 4; bi++) {
                    const float* hq = sm + SH_OFF + (bg + 8 * bi) * 516 +
                                      ch * 128 + hf * 64 + ks * 8;
                    const float* cq = sm + SC_OFF + (bg + 8 * bi) * 516 +
                                      ch * 128 + hf * 64 + ks * 8;
                    hv[bi][0] = *(const ulonglong2*)hq;
                    hv[bi][1] = *(const ulonglong2*)(hq + 4);
                    cv[bi][0] = *(const ulonglong2*)cq;
                    cv[bi][1] = *(const ulonglong2*)(cq + 4);
                }
#pragma unroll
                for (int g = 0; g < 5; g++) {
#pragma unroll
                    for (int ji = 0; ji < 2; ji++) {
                        const float* wp = sm + SW_OFF +
                            (g * 8 + jg * 2 + ji) * 516 +
                            ch * 128 + hf * 64 + ks * 8;
                        ulonglong2 w0 = *(const ulonglong2*)wp;
                        ulonglong2 w1 = *(const ulonglong2*)(wp + 4);
                        if (g < 4) {
#pragma unroll
                            for (int bi = 0; bi < 4; bi++) {
                                ffma2(acc[g][ji][bi], hv[bi][0].x, w0.x);
                                ffma2(acc[g][ji][bi], hv[bi][0].y, w0.y);
                                ffma2(acc[g][ji][bi], hv[bi][1].x, w1.x);
                                ffma2(acc[g][ji][bi], hv[bi][1].y, w1.y);
                            }
                        } else {
#pragma unroll
                            for (int bi = 0; bi < 4; bi++) {
                                ffma2(acc[g][ji][bi], cv[bi][0].x, w0.x);
                                ffma2(acc[g][ji][bi], cv[bi][0].y, w0.y);
                                ffma2(acc[g][ji][bi], cv[bi][1].x, w1.x);
                                ffma2(acc[g][ji][bi], cv[bi][1].y, w1.y);
                            }
                        }
                    }
                }
            }
        }
        __syncthreads();  // all compute reads done; reduction aliases state

        // Partial scatter: R[ks][slot][cell], lanes=cells -> conflict-free
        {
            float* R = sm + SRED_OFF + ks * 1280 + (t & 31);
#pragma unroll
            for (int g = 0; g < 5; g++)
#pragma unroll
                for (int ji = 0; ji < 2; ji++)
#pragma unroll
                    for (int bi = 0; bi < 4; bi++)
                        R[(g * 8 + ji * 4 + bi) * 32] =
                            lo32(acc[g][ji][bi]) + hi32(acc[g][ji][bi]);
        }
        __syncthreads();

        // Gather across 8 k-slices + gate epilogue
        {
            float sum0 = 0.f, sum1 = 0.f, sum2 = 0.f, sum3 = 0.f, sum4 = 0.f;
#pragma unroll
            for (int k2 = 0; k2 < 8; k2++) {
                const float* R = sm + SRED_OFF + k2 * 1280 + idxb * 32 + cell;
                sum0 += R[0 * 256];
                sum1 += R[1 * 256];
                sum2 += R[2 * 256];
                sum3 += R[3 * 256];
                sum4 += R[4 * 256];
            }
            float pf = sum0 + zbf + uf;
            float pi = sum1 + zbi + ui;
            float po = sum2 + zbo + uo;
            float pg = sum3 + zbg + ug;
            float dd = sum4 + zbd;

            float cs1 = tanha(dd);
            float cadj = (cold - cs1) + cs1 * tsv;
            float fg = sigm(pf);
            float ig = sigm(pi);
            float og = sigm(po);
            float cg = sigm(pg);
            float cnew = fg * cadj + ig * cg;
            float hnew = og * tanha(cnew);

            __stcg(hn + (size_t)ebg * HH + ej, hnew);
            __stcg(cn + (size_t)ebg * HH + ej, cnew);
            out[((size_t)ebg * SS + s) * HH + ej] = hnew;

            if (s == SS - 1 && write_tail) {
                out[(size_t)BB * SS * HH + (size_t)ebg * HH + ej] = hnew;
                out[(size_t)BB * SS * HH + (size_t)BB * HH +
                    (size_t)ebg * HH + ej] = cnew;
            }
        }

        // Grid barrier
        __syncthreads();
        if (t == 0) {
            __threadfence();
            unsigned old = atomicAdd(&g_cnt, 1);
            if (old == NBLK - 1) {
                g_cnt = 0;
                unsigned gv = (unsigned)(s + 1);
                asm volatile("st.release.gpu.global.u32 [%0], %1;"
                             :: "l"(&g_gen), "r"(gv) : "memory");
            } else {
                unsigned v;
                do {
                    asm volatile("ld.acquire.gpu.global.u32 %0, [%1];"
                                 : "=r"(v) : "l"(&g_gen) : "memory");
                } while (v < (unsigned)(s + 1));
            }
        }
        __syncthreads();
    }
}

// ---------------------------------------------------------------------------
extern "C" void kernel_launch(void* const* d_in, const int* in_sizes, int n_in,
                              void* d_out, int out_size) {
    const float* X      = (const float*)d_in[0];
    const float* ts     = (const float*)d_in[1];
    const float* Wall   = (const float*)d_in[2];
    const float* Wall_b = (const float*)d_in[3];
    const float* U      = (const float*)d_in[4];
    const float* Ub     = (const float*)d_in[5];
    const float* Wd     = (const float*)d_in[6];
    const float* Wdb    = (const float*)d_in[7];
    float* out = (float*)d_out;

    cudaFuncSetAttribute(lstm_persistent,
                         cudaFuncAttributeMaxDynamicSharedMemorySize,
                         SM_TOTF * (int)sizeof(float));

    init_state_kernel<<<(BB * HH + 255) / 256, 256>>>();

    dim3 gu(SS * 2, FH / 128);
    u_gemm_kernel<<<gu, 256>>>(X, U, Ub);

    long long need = (long long)BB * SS * HH + 2LL * BB * HH;
    int write_tail = ((long long)out_size >= need) ? 1 : 0;

    lstm_persistent<<<NBLK, NT, SM_TOTF * sizeof(float)>>>(
        Wall, Wall_b, Wd, Wdb, ts, out, write_tail);
}

// round 9
// speedup vs baseline: 3.2013x; 1.0008x over previous
#include <cuda_runtime.h>
#include <cstdint>

#define BB 64
#define SS 512
#define EE 256
#define HH 512
#define FH 2048
#define NBLK 128
#define NT 256

__device__ float g_hs[2][BB * HH];
__device__ float g_cs[2][BB * HH];
__device__ float g_u[(size_t)SS * BB * FH];  // [s][b][4H]
__device__ unsigned g_cnt, g_gen;

// Shared memory float offsets (persistent kernel)
#define SW_OFF 0
#define SW_SZ (5 * 8 * 516)             // 20640: weights [40 rows][516]
#define SH_OFF SW_SZ                    // h state [32 b][516]
#define SC_OFF (SH_OFF + 32 * 516)      // c state [32 b][516]
#define SRED_OFF SH_OFF                 // reduction ALIASES state (post-compute)
#define SM_TOTF (SC_OFF + 32 * 516)     // 53664 floats = 214656 B

// ---------------------------------------------------------------------------
__device__ __forceinline__ void ffma2(unsigned long long& d,
                                      unsigned long long a,
                                      unsigned long long b) {
    asm volatile("fma.rn.f32x2 %0, %1, %2, %0;" : "+l"(d) : "l"(a), "l"(b));
}
__device__ __forceinline__ float lo32(unsigned long long v) {
    return __uint_as_float((unsigned)(v & 0xffffffffull));
}
__device__ __forceinline__ float hi32(unsigned long long v) {
    return __uint_as_float((unsigned)(v >> 32));
}
__device__ __forceinline__ float tanha(float x) {
    float y;
    asm("tanh.approx.f32 %0, %1;" : "=f"(y) : "f"(x));
    return y;
}
__device__ __forceinline__ float sigm(float x) {
    return 0.5f * tanha(0.5f * x) + 0.5f;
}
__device__ __forceinline__ uint32_t smem_u32(const void* p) {
    uint32_t a;
    asm("{ .reg .u64 t; cvta.to.shared.u64 t, %1; cvt.u32.u64 %0, t; }"
        : "=r"(a) : "l"(p));
    return a;
}
__device__ __forceinline__ void cpasync16(uint32_t dst, const void* src) {
    asm volatile("cp.async.cg.shared.global [%0], [%1], 16;"
                 :: "r"(dst), "l"(src));
}
#define CP_COMMIT() asm volatile("cp.async.commit_group;")
#define CP_WAIT(n)  asm volatile("cp.async.wait_group %0;" :: "n"(n))

// ---------------------------------------------------------------------------
__global__ void init_state_kernel() {
    int i = blockIdx.x * blockDim.x + threadIdx.x;
    if (i < BB * HH) {
        g_hs[0][i] = 0.f;
        g_cs[0][i] = 0.f;
    }
    if (i == 0) { g_cnt = 0; g_gen = 0; }
}

// ---------------------------------------------------------------------------
// u_all GEMM (batch-packed FFMA2). Output: g_u[s][b][4H].
// ---------------------------------------------------------------------------
#define UG_KC 32

__global__ __launch_bounds__(256) void u_gemm_kernel(
    const float* __restrict__ X,
    const float* __restrict__ W,
    const float* __restrict__ Bv)
{
    __shared__ float2 sA[16][UG_KC];
    __shared__ float2 sB[128][UG_KC + 2];

    int t = threadIdx.x;
    int tx = t & 15;
    int ty = t >> 4;
    int s  = blockIdx.x >> 1;
    int bh = blockIdx.x & 1;
    int b0 = bh * 32;
    int n0 = blockIdx.y * 128;

    unsigned long long acc[8];
#pragma unroll
    for (int i = 0; i < 8; i++) acc[i] = 0ull;

    for (int k0 = 0; k0 < EE; k0 += UG_KC) {
#pragma unroll
        for (int r = 0; r < 2; r++) {
            int i = t + 256 * r;
            int p = i >> 5, k = i & 31;
            int b = b0 + 2 * p;
            float x0 = X[((size_t)b * SS + s) * EE + k0 + k];
            float x1 = X[((size_t)(b + 1) * SS + s) * EE + k0 + k];
            sA[p][k] = make_float2(x0, x1);
        }
#pragma unroll
        for (int r = 0; r < 16; r++) {
            int i = t + 256 * r;
            int n = i >> 5, k = i & 31;
            float w = W[(size_t)(n0 + n) * EE + k0 + k];
            sB[n][k] = make_float2(w, w);
        }
        __syncthreads();
#pragma unroll
        for (int k = 0; k < UG_KC; k += 2) {
            unsigned long long a0 = *(const unsigned long long*)&sA[ty][k];
            unsigned long long a1 = *(const unsigned long long*)&sA[ty][k + 1];
#pragma unroll
            for (int n8 = 0; n8 < 8; n8++) {
                const unsigned long long* bp =
                    (const unsigned long long*)&sB[tx + 16 * n8][k];
                ffma2(acc[n8], a0, bp[0]);
                ffma2(acc[n8], a1, bp[1]);
            }
        }
        __syncthreads();
    }

    int p = b0 / 2 + ty;
#pragma unroll
    for (int n8 = 0; n8 < 8; n8++) {
        int n = n0 + tx + 16 * n8;
        float bv = Bv[n];
        g_u[((size_t)s * BB + 2 * p) * FH + n]     = lo32(acc[n8]) + bv;
        g_u[((size_t)s * BB + 2 * p + 1) * FH + n] = hi32(acc[n8]) + bv;
    }
}

// ---------------------------------------------------------------------------
// Persistent recurrence. 128 blocks = 64 j-tiles(8) x 2 batch-halves(32).
// Thread t: ks = t>>5, jg = (t>>3)&3, bg = t&7. Mb=4 batches, Nb=2 j.
// Whole state staged at step start (4 cp.async groups, one per 128-k chunk);
// weights smem-resident for all 512 steps; final h/c tail written in-kernel.
// ---------------------------------------------------------------------------
__global__ __launch_bounds__(NT, 1) void lstm_persistent(
    const float* __restrict__ Wall,
    const float* __restrict__ Wall_b,
    const float* __restrict__ Wd,
    const float* __restrict__ Wd_b,
    const float* __restrict__ ts,
    float* __restrict__ out,
    int write_tail)
{
    extern __shared__ float sm[];
    const uint32_t smb = smem_u32(sm);

    const int t  = threadIdx.x;
    const int ks = t >> 5;
    const int jg = (t >> 3) & 3;
    const int bg = t & 7;
    const int jt = blockIdx.x >> 1;
    const int bh = blockIdx.x & 1;
    const int j0 = jt * 8;

    // Epilogue identity
    const int eb  = t >> 3;
    const int ejl = t & 7;
    const int ej  = j0 + ejl;
    const int ebg = bh * 32 + eb;
    const int cell = (ejl >> 1) * 8 + (eb & 7);
    const int idxb = (ejl & 1) * 4 + (eb >> 3);

    // One-time weight slice load: rows [g*8+jl][516]
#pragma unroll 4
    for (int it = 0; it < 80; it++) {
        int i = t + NT * it;
        int g = i >> 12;
        int jl = (i >> 9) & 7;
        int k = i & 511;
        float w = (g < 4) ? Wall[(size_t)(g * HH + j0 + jl) * HH + k]
                          : Wd[(size_t)(j0 + jl) * HH + k];
        sm[SW_OFF + (g * 8 + jl) * 516 + k] = w;
    }
    const float zbf = Wall_b[ej];
    const float zbi = Wall_b[HH + ej];
    const float zbo = Wall_b[2 * HH + ej];
    const float zbg = Wall_b[3 * HH + ej];
    const float zbd = Wd_b[ej];
    __syncthreads();

    for (int s = 0; s < SS; s++) {
        const int par = s & 1;
        const float* hp = g_hs[par];
        const float* cp = g_cs[par];
        float* hn = g_hs[par ^ 1];
        float* cn = g_cs[par ^ 1];

        // Epilogue operand prefetch (arrives under the k-loop)
        const float* ub = g_u + ((size_t)s * BB + ebg) * FH;
        float uf = __ldcs(ub + ej);
        float ui = __ldcs(ub + HH + ej);
        float uo = __ldcs(ub + 2 * HH + ej);
        float ug = __ldcs(ub + 3 * HH + ej);
        float cold = __ldcg(cp + (size_t)ebg * HH + ej);
        float tsv = __ldg(ts + (size_t)ebg * SS + s);

        // Issue ALL state staging up-front: 4 groups (one per 128-k chunk)
#pragma unroll
        for (int ch = 0; ch < 4; ch++) {
#pragma unroll
            for (int q = 0; q < 8; q++) {
                int o = t + NT * (q & 3);
                int b = o >> 5;          // 0..31
                int k4 = o & 31;         // 0..31 (x4 floats)
                int koff = ch * 128 + k4 * 4;
                if (q < 4) {
                    cpasync16(smb + (uint32_t)((SH_OFF + b * 516 + koff) * 4),
                              hp + (size_t)(bh * 32 + b) * HH + koff);
                } else {
                    cpasync16(smb + (uint32_t)((SC_OFF + b * 516 + koff) * 4),
                              cp + (size_t)(bh * 32 + b) * HH + koff);
                }
            }
            CP_COMMIT();
        }

        unsigned long long acc[5][2][4];
#pragma unroll
        for (int g = 0; g < 5; g++)
#pragma unroll
            for (int ji = 0; ji < 2; ji++)
#pragma unroll
                for (int bi = 0; bi < 4; bi++) acc[g][ji][bi] = 0ull;

#pragma unroll 1
        for (int ch = 0; ch < 4; ch++) {
            switch (ch) {
                case 0: CP_WAIT(3); break;
                case 1: CP_WAIT(2); break;
                case 2: CP_WAIT(1); break;
                default: CP_WAIT(0); break;
            }
            __syncthreads();

#pragma unroll
            for (int hf = 0; hf < 2; hf++) {
                ulonglong2 hv[4][2], cv[4][2];
#pragma unroll
                for (int bi = 0; bi < 4; bi++) {
                    const float* hq = sm + SH_OFF + (bg + 8 * bi) * 516 +
                                      ch * 128 + hf * 64 + ks * 8;
                    const float* cq = sm + SC_OFF + (bg + 8 * bi) * 516 +
                                      ch * 128 + hf * 64 + ks * 8;
                    hv[bi][0] = *(const ulonglong2*)hq;
                    hv[bi][1] = *(const ulonglong2*)(hq + 4);
                    cv[bi][0] = *(const ulonglong2*)cq;
                    cv[bi][1] = *(const ulonglong2*)(cq + 4);
                }
#pragma unroll
                for (int g = 0; g < 5; g++) {
#pragma unroll
                    for (int ji = 0; ji < 2; ji++) {
                        const float* wp = sm + SW_OFF +
                            (g * 8 + jg * 2 + ji) * 516 +
                            ch * 128 + hf * 64 + ks * 8;
                        ulonglong2 w0 = *(const ulonglong2*)wp;
                        ulonglong2 w1 = *(const ulonglong2*)(wp + 4);
                        if (g < 4) {
#pragma unroll
                            for (int bi = 0; bi < 4; bi++) {
                                ffma2(acc[g][ji][bi], hv[bi][0].x, w0.x);
                                ffma2(acc[g][ji][bi], hv[bi][0].y, w0.y);
                                ffma2(acc[g][ji][bi], hv[bi][1].x, w1.x);
                                ffma2(acc[g][ji][bi], hv[bi][1].y, w1.y);
                            }
                        } else {
#pragma unroll
                            for (int bi = 0; bi < 4; bi++) {
                                ffma2(acc[g][ji][bi], cv[bi][0].x, w0.x);
                                ffma2(acc[g][ji][bi], cv[bi][0].y, w0.y);
                                ffma2(acc[g][ji][bi], cv[bi][1].x, w1.x);
                                ffma2(acc[g][ji][bi], cv[bi][1].y, w1.y);
                            }
                        }
                    }
                }
            }
        }
        __syncthreads();  // all compute reads done; reduction aliases state

        // Partial scatter: R[ks][slot][cell], lanes=cells -> conflict-free
        {
            float* R = sm + SRED_OFF + ks * 1280 + (t & 31);
#pragma unroll
            for (int g = 0; g < 5; g++)
#pragma unroll
                for (int ji = 0; ji < 2; ji++)
#pragma unroll
                    for (int bi = 0; bi < 4; bi++)
                        R[(g * 8 + ji * 4 + bi) * 32] =
                            lo32(acc[g][ji][bi]) + hi32(acc[g][ji][bi]);
        }
        __syncthreads();

        // Gather across 8 k-slices + gate epilogue
        {
            float sum0 = 0.f, sum1 = 0.f, sum2 = 0.f, sum3 = 0.f, sum4 = 0.f;
#pragma unroll
            for (int k2 = 0; k2 < 8; k2++) {
                const float* R = sm + SRED_OFF + k2 * 1280 + idxb * 32 + cell;
                sum0 += R[0 * 256];
                sum1 += R[1 * 256];
                sum2 += R[2 * 256];
                sum3 += R[3 * 256];
                sum4 += R[4 * 256];
            }
            float pf = sum0 + zbf + uf;
            float pi = sum1 + zbi + ui;
            float po = sum2 + zbo + uo;
            float pg = sum3 + zbg + ug;
            float dd = sum4 + zbd;

            float cs1 = tanha(dd);
            float cadj = (cold - cs1) + cs1 * tsv;
            float fg = sigm(pf);
            float ig = sigm(pi);
            float og = sigm(po);
            float cg = sigm(pg);
            float cnew = fg * cadj + ig * cg;
            float hnew = og * tanha(cnew);

            __stcg(hn + (size_t)ebg * HH + ej, hnew);
            __stcg(cn + (size_t)ebg * HH + ej, cnew);
            out[((size_t)ebg * SS + s) * HH + ej] = hnew;

            if (s == SS - 1 && write_tail) {
                out[(size_t)BB * SS * HH + (size_t)ebg * HH + ej] = hnew;
                out[(size_t)BB * SS * HH + (size_t)BB * HH +
                    (size_t)ebg * HH + ej] = cnew;
            }
        }

        // Grid barrier
        __syncthreads();
        if (t == 0) {
            __threadfence();
            unsigned old = atomicAdd(&g_cnt, 1);
            if (old == NBLK - 1) {
                g_cnt = 0;
                unsigned gv = (unsigned)(s + 1);
                asm volatile("st.release.gpu.global.u32 [%0], %1;"
                             :: "l"(&g_gen), "r"(gv) : "memory");
            } else {
                unsigned v;
                do {
                    asm volatile("ld.acquire.gpu.global.u32 %0, [%1];"
                                 : "=r"(v) : "l"(&g_gen) : "memory");
                } while (v < (unsigned)(s + 1));
            }
        }
        __syncthreads();
    }
}

// ---------------------------------------------------------------------------
extern "C" void kernel_launch(void* const* d_in, const int* in_sizes, int n_in,
                              void* d_out, int out_size) {
    const float* X      = (const float*)d_in[0];
    const float* ts     = (const float*)d_in[1];
    const float* Wall   = (const float*)d_in[2];
    const float* Wall_b = (const float*)d_in[3];
    const float* U      = (const float*)d_in[4];
    const float* Ub     = (const float*)d_in[5];
    const float* Wd     = (const float*)d_in[6];
    const float* Wdb    = (const float*)d_in[7];
    float* out = (float*)d_out;

    cudaFuncSetAttribute(lstm_persistent,
                         cudaFuncAttributeMaxDynamicSharedMemorySize,
                         SM_TOTF * (int)sizeof(float));

    init_state_kernel<<<(BB * HH + 255) / 256, 256>>>();

    dim3 gu(SS * 2, FH / 128);
    u_gemm_kernel<<<gu, 256>>>(X, U, Ub);

    long long need = (long long)BB * SS * HH + 2LL * BB * HH;
    int write_tail = ((long long)out_size >= need) ? 1 : 0;

    lstm_persistent<<<NBLK, NT, SM_TOTF * sizeof(float)>>>(
        Wall, Wall_b, Wd, Wdb, ts, out, write_tail);
}